// round 7
// baseline (speedup 1.0000x reference)
#include <cuda_runtime.h>
#include <climits>

// Problem constants
#define T_    30
#define H_    41
#define WD_   2048
#define NSEC  9
#define FM_   50
#define KH_   6
#define KW_   40
#define WP_   502          // pooled width
#define THRESH 23.0f

#define XROWS 9            // rows per section
#define XPITCH 552         // 512 chunk + 39 halo + pad -> multiple of 4
#define CHUNK 512
#define WSECF (FM_*KH_*KW_)   // 12000 floats per section

// pooled elements then 9 feat values
#define POOLED_ELEMS (NSEC*T_*FM_*WP_)   // 6,777,000

__device__ int g_key[NSEC];

__global__ void init_keys_kernel() {
    if (threadIdx.x < NSEC) g_key[threadIdx.x] = INT_MAX;
}

__device__ __forceinline__ unsigned long long dup2(float v) {
    unsigned long long r;
    unsigned u = __float_as_uint(v);
    asm("mov.b64 %0, {%1, %1};" : "=l"(r) : "r"(u));
    return r;
}
__device__ __forceinline__ void fma2(unsigned long long &d,
                                     unsigned long long a,
                                     unsigned long long b) {
    // packed fp32x2 FMA (Blackwell FFMA2) -- exact fp32 rounding per lane
    asm("fma.rn.f32x2 %0, %1, %2, %0;" : "+l"(d) : "l"(a), "l"(b));
}

// grid: 1080 = 9 sec * 30 t * 4 chunks ; block: 640 threads = 20 warps
// warp layout: fm_group = wid/4 (5 groups of 10 fm), subgroup = wid%4
// thread: 10 fm x 4 ow (one pool window) x 4 oh
__global__ __launch_bounds__(640, 1)
void conv_main_kernel(const float* __restrict__ x,
                      const float* __restrict__ Wt,
                      float* __restrict__ out)
{
    extern __shared__ float sm[];
    float* xs = sm;                 // XROWS * XPITCH
    float* ws = sm + XROWS*XPITCH;  // WSECF, layout [(kh*40+kw)*50 + fm]

    const int bx    = blockIdx.x;
    const int sec   = bx / 120;
    const int rem   = bx - sec*120;
    const int t     = rem >> 2;
    const int chunk = rem & 3;
    const int col0  = chunk << 9;   // chunk * 512

    // ---- stage x section rows (with halo, zero-fill past WD_) ----
    const float* xg = x + (t*H_ + 4*sec) * WD_;
    for (int i = threadIdx.x; i < XROWS*XPITCH; i += 640) {
        int r = i / XPITCH;
        int c = i - r*XPITCH;
        int gc = col0 + c;
        xs[i] = (gc < WD_) ? xg[r*WD_ + gc] : 0.0f;
    }
    // ---- stage section weights: coalesced gmem read, transposed store ----
    const float* wg = Wt + sec * WSECF;
    for (int i = threadIdx.x; i < WSECF; i += 640) {
        int fm = i / 240;           // 240 = KH*KW
        int r  = i - fm*240;        // r = kh*40 + kw
        ws[r*FM_ + fm] = wg[i];
    }
    __syncthreads();

    const int wid   = threadIdx.x >> 5;
    const int lane  = threadIdx.x & 31;
    const int fg    = wid >> 2;            // 0..4
    const int sub   = wid & 3;             // 0..3
    const int tile  = sub*32 + lane;       // 0..127
    const int owl   = tile << 2;           // local ow base (mult of 4)
    const int fmbase = fg * 10;
    const int gow   = col0 + owl;          // global ow base
    const bool valid = (gow <= 2004);      // gow+3 <= 2007

    unsigned pooled = 0;                    // 10 bits, one per fm

    #pragma unroll 1
    for (int oh = 0; oh < 4; ++oh) {
        unsigned long long acc[5][4];
        #pragma unroll
        for (int p = 0; p < 5; ++p)
            #pragma unroll
            for (int j = 0; j < 4; ++j) acc[p][j] = 0ull;

        #pragma unroll 1
        for (int kh = 0; kh < KH_; ++kh) {
            const float* xr = xs + (oh + kh)*XPITCH + owl;
            const float* wr = ws + kh*(KW_*FM_) + fmbase;

            // register ring of 4 duplicated x values: window for kw=0
            float4 v0 = *(const float4*)xr;     // 16B aligned (owl%4==0, pitch%4==0)
            unsigned long long ring[4];
            ring[0] = dup2(v0.x); ring[1] = dup2(v0.y);
            ring[2] = dup2(v0.z); ring[3] = dup2(v0.w);

            #pragma unroll 2
            for (int kw0 = 0; kw0 < KW_; kw0 += 4) {
                float4 inc = *(const float4*)(xr + kw0 + 4);  // next 4 x values
                #pragma unroll
                for (int u = 0; u < 4; ++u) {
                    const float* wkw = wr + (kw0 + u)*FM_;
                    unsigned long long w0 = *(const unsigned long long*)(wkw + 0);
                    unsigned long long w1 = *(const unsigned long long*)(wkw + 2);
                    unsigned long long w2 = *(const unsigned long long*)(wkw + 4);
                    unsigned long long w3 = *(const unsigned long long*)(wkw + 6);
                    unsigned long long w4 = *(const unsigned long long*)(wkw + 8);
                    #pragma unroll
                    for (int j = 0; j < 4; ++j) {
                        unsigned long long xv = ring[(u + j) & 3];
                        fma2(acc[0][j], w0, xv);
                        fma2(acc[1][j], w1, xv);
                        fma2(acc[2][j], w2, xv);
                        fma2(acc[3][j], w3, xv);
                        fma2(acc[4][j], w4, xv);
                    }
                    // slot u is dead for the rest of this 4-step group;
                    // install x[owl + kw0 + 4 + u] for the next steps
                    ring[u] = dup2(u == 0 ? inc.x : u == 1 ? inc.y
                                 : u == 2 ? inc.z : inc.w);
                }
            }
        }
        // threshold + 4x4 pool (j covers the 4 ow of this thread's window;
        // OR across oh happens across the outer loop)
        #pragma unroll
        for (int p = 0; p < 5; ++p)
            #pragma unroll
            for (int j = 0; j < 4; ++j) {
                float lo = __uint_as_float((unsigned)(acc[p][j]));
                float hi = __uint_as_float((unsigned)(acc[p][j] >> 32));
                if (lo > THRESH) pooled |= 1u << (2*p);
                if (hi > THRESH) pooled |= 1u << (2*p + 1);
            }
    }

    const int wp = gow >> 2;
    if (valid) {
        float* ob = out + ((sec*T_ + t)*FM_ + fmbase)*WP_ + wp;
        #pragma unroll
        for (int f = 0; f < 10; ++f)
            ob[f*WP_] = ((pooled >> f) & 1u) ? 1.0f : 0.0f;
    }

    // winner-take-all key: lexicographic (t_first, fm*502+wp) packed
    unsigned key = 0x7fffffffu;
    if (valid && pooled) {
        int f0 = __ffs(pooled) - 1;   // smallest fm bit -> smallest cell index
        key = (unsigned)((t << 15) | ((fmbase + f0)*WP_ + wp));
    }
    #pragma unroll
    for (int o = 16; o; o >>= 1) {
        unsigned other = __shfl_xor_sync(0xffffffffu, key, o);
        key = (other < key) ? other : key;
    }
    if (lane == 0 && key != 0x7fffffffu)
        atomicMin(&g_key[sec], (int)key);
}

__global__ void finalize_kernel(float* __restrict__ out, long long out_size) {
    int s = threadIdx.x;
    if (s < NSEC && out_size >= (long long)(POOLED_ELEMS + NSEC)) {
        int k = g_key[s];
        out[POOLED_ELEMS + s] =
            (k == INT_MAX) ? -1.0f : (float)((k & 32767) / WP_);
    }
}

extern "C" void kernel_launch(void* const* d_in, const int* in_sizes, int n_in,
                              void* d_out, int out_size) {
    const float* x = (const float*)d_in[0];
    const float* W = (const float*)d_in[1];
    // defensive: swap if metadata order differs (x has 2,519,040 elems, W 108,000)
    if (n_in >= 2 && in_sizes[0] == NSEC*FM_*KH_*KW_) {
        const float* tmp = x; x = W; W = tmp;
    }
    float* out = (float*)d_out;

    const size_t smem = (XROWS*XPITCH + WSECF) * sizeof(float);  // ~66.3 KB
    cudaFuncSetAttribute(conv_main_kernel,
                         cudaFuncAttributeMaxDynamicSharedMemorySize, (int)smem);

    init_keys_kernel<<<1, 32>>>();
    conv_main_kernel<<<NSEC*T_*4, 640, smem>>>(x, W, out);
    finalize_kernel<<<1, 32>>>(out, (long long)out_size);
}